// round 7
// baseline (speedup 1.0000x reference)
#include <cuda_runtime.h>
#include <math.h>

#define N_CLASSES 1000
#define L4        250          // label row in float4s (1000/4)
#define EMBED     1024
#define THREADS   256
#define WPB       8            // warps (rows) per block
#define GRID      4096         // 32768 / WPB

__device__ float        g_acc;     // zero-initialized at module load
__device__ unsigned int g_count;   // reset to 0 by last block each run

__global__ void __launch_bounds__(THREADS, 1)
angular_loss_kernel(const float* __restrict__ features,
                    const float* __restrict__ labels,
                    const float* __restrict__ mean_class,
                    float* __restrict__ out,
                    int N)
{
    const int warp = threadIdx.x >> 5;
    const int lane = threadIdx.x & 31;
    const int row  = blockIdx.x * WPB + warp;

    __shared__ float s_part[WPB];

    const float4* lrow = reinterpret_cast<const float4*>(
        labels + (size_t)row * N_CLASSES);
    const float4* frow = reinterpret_cast<const float4*>(
        features + (size_t)row * EMBED);

    // ---- front-batch the feature stream (always needed, fills pipeline) ----
    float4 fv[8];
    #pragma unroll
    for (int k = 0; k < 8; k++)
        fv[k] = __ldcs(&frow[k * 32 + lane]);

    // ---- early-exit label scan: 128-float chunks, depth-2 lookahead ----
    float4 cur = __ldcs(&lrow[lane]);          // chunk 0
    float4 nxt = __ldcs(&lrow[32 + lane]);     // chunk 1
    int   c = -1;
    float v = 0.0f;

    #pragma unroll
    for (int i = 0; i < 8; i++) {
        int   c_loc = -1;
        float v_loc = 0.0f;
        const int base = (i * 32 + lane) * 4;
        if (cur.x != 0.0f) { c_loc = base + 0; v_loc = cur.x; }
        if (cur.y != 0.0f) { c_loc = base + 1; v_loc = cur.y; }
        if (cur.z != 0.0f) { c_loc = base + 2; v_loc = cur.z; }
        if (cur.w != 0.0f) { c_loc = base + 3; v_loc = cur.w; }

        const unsigned found = __ballot_sync(0xFFFFFFFFu, c_loc >= 0);
        if (found) {                       // warp-uniform: safe uniform break
            const int src = __ffs(found) - 1;
            c = __shfl_sync(0xFFFFFFFFu, c_loc, src);
            v = __shfl_sync(0xFFFFFFFFu, v_loc, src);
            break;
        }
        if (i + 2 < 8) {                   // issue chunk i+2, rotate buffers
            const int idx = (i + 2) * 32 + lane;
            float4 t = (idx < L4) ? __ldcs(&lrow[idx])
                                  : make_float4(0.f, 0.f, 0.f, 0.f);
            cur = nxt;
            nxt = t;
        } else {
            cur = nxt;
        }
    }
    if (c < 0) { c = 0; v = 0.0f; }        // no nonzero: matches ref (cos=0)

    // ---- gather mean_class[c] (L2-hot) and compute ff, pp, fp ----
    const float4* mrow = reinterpret_cast<const float4*>(
        mean_class + (size_t)c * EMBED);
    float4 mv[8];
    #pragma unroll
    for (int k = 0; k < 8; k++) mv[k] = __ldg(&mrow[k * 32 + lane]);

    float ff = 0.0f, pp = 0.0f, fp = 0.0f;
    #pragma unroll
    for (int k = 0; k < 8; k++) {
        const float4 f = fv[k];
        const float4 m = mv[k];
        ff += f.x*f.x + f.y*f.y + f.z*f.z + f.w*f.w;
        pp += m.x*m.x + m.y*m.y + m.z*m.z + m.w*m.w;
        fp += f.x*m.x + f.y*m.y + f.z*m.z + f.w*m.w;
    }
    #pragma unroll
    for (int off = 16; off > 0; off >>= 1) {
        ff += __shfl_xor_sync(0xFFFFFFFFu, ff, off);
        pp += __shfl_xor_sync(0xFFFFFFFFu, pp, off);
        fp += __shfl_xor_sync(0xFFFFFFFFu, fp, off);
    }

    if (lane == 0) {
        const float eps = 1e-12f;
        const float nf   = fmaxf(sqrtf(ff), eps);
        const float np   = fmaxf(fabsf(v) * sqrtf(pp), eps);
        const float cosv = (v * fp) / (nf * np);
        s_part[warp] = 1.0f - cosv;
    }
    __syncthreads();

    // ---- block partial -> global accumulator; last block finishes ----
    if (threadIdx.x == 0) {
        float s = 0.0f;
        #pragma unroll
        for (int w = 0; w < WPB; w++) s += s_part[w];
        atomicAdd(&g_acc, s / (float)N);
        __threadfence();
        const unsigned ticket = atomicAdd(&g_count, 1u);
        if (ticket == (unsigned)(gridDim.x - 1)) {
            out[0] = g_acc;           // all prior adds visible via fence+ticket
            g_acc   = 0.0f;           // reset for next graph replay
            g_count = 0u;
        }
    }
}

extern "C" void kernel_launch(void* const* d_in, const int* in_sizes, int n_in,
                              void* d_out, int out_size)
{
    const float* features   = (const float*)d_in[0];
    const float* labels     = (const float*)d_in[1];
    const float* mean_class = (const float*)d_in[2];
    float* out = (float*)d_out;

    const int N = in_sizes[0] / EMBED;   // 32768

    angular_loss_kernel<<<GRID, THREADS>>>(
        features, labels, mean_class, out, N);
}

// round 8
// speedup vs baseline: 1.2157x; 1.2157x over previous
#include <cuda_runtime.h>
#include <math.h>

#define N_CLASSES 1000
#define L4        250          // label row in float4s (1000/4)
#define EMBED     1024
#define THREADS   256
#define WPB       8            // warps (rows) per block
#define GRID      4096         // 32768 / WPB

__device__ float        g_acc;     // zero-initialized at module load
__device__ unsigned int g_count;   // reset to 0 by last block each run

__global__ void __launch_bounds__(THREADS, 1)
angular_loss_kernel(const float* __restrict__ features,
                    const float* __restrict__ labels,
                    const float* __restrict__ mean_class,
                    float* __restrict__ out,
                    int N)
{
    const int warp = threadIdx.x >> 5;
    const int lane = threadIdx.x & 31;
    const int row  = blockIdx.x * WPB + warp;

    __shared__ float s_part[WPB];

    const float4* lrow = reinterpret_cast<const float4*>(
        labels + (size_t)row * N_CLASSES);
    const float4* frow = reinterpret_cast<const float4*>(
        features + (size_t)row * EMBED);

    // ---- front batch: 6 label chunks (floats 0..767), then 8 feature chunks.
    //      Labels issued first so they land first; features keep the DRAM
    //      pipe busy while this warp resolves the one-hot.
    float4 lv[6];
    #pragma unroll
    for (int k = 0; k < 6; k++)
        lv[k] = __ldcs(&lrow[k * 32 + lane]);

    float4 fv[8];
    #pragma unroll
    for (int k = 0; k < 8; k++)
        fv[k] = __ldcs(&frow[k * 32 + lane]);

    // ---- resolve from the first 768 floats (p ~= 0.768) ----
    int   c_loc = -1;
    float v_loc = 0.0f;
    #pragma unroll
    for (int k = 0; k < 6; k++) {
        const int base = (k * 32 + lane) * 4;
        if (lv[k].x != 0.0f) { c_loc = base + 0; v_loc = lv[k].x; }
        if (lv[k].y != 0.0f) { c_loc = base + 1; v_loc = lv[k].y; }
        if (lv[k].z != 0.0f) { c_loc = base + 2; v_loc = lv[k].z; }
        if (lv[k].w != 0.0f) { c_loc = base + 3; v_loc = lv[k].w; }
    }
    unsigned found = __ballot_sync(0xFFFFFFFFu, c_loc >= 0);

    // ---- rare second batch: floats 768..999 (warp-uniform branch) ----
    if (!found) {
        const float4 e0 = __ldcs(&lrow[192 + lane]);               // chunk 6
        const int idx7 = 224 + lane;
        const float4 e1 = (idx7 < L4) ? __ldcs(&lrow[idx7])        // chunk 7
                                      : make_float4(0.f, 0.f, 0.f, 0.f);
        const int b0 = (192 + lane) * 4;
        if (e0.x != 0.0f) { c_loc = b0 + 0; v_loc = e0.x; }
        if (e0.y != 0.0f) { c_loc = b0 + 1; v_loc = e0.y; }
        if (e0.z != 0.0f) { c_loc = b0 + 2; v_loc = e0.z; }
        if (e0.w != 0.0f) { c_loc = b0 + 3; v_loc = e0.w; }
        const int b1 = idx7 * 4;
        if (e1.x != 0.0f) { c_loc = b1 + 0; v_loc = e1.x; }
        if (e1.y != 0.0f) { c_loc = b1 + 1; v_loc = e1.y; }
        if (e1.z != 0.0f) { c_loc = b1 + 2; v_loc = e1.z; }
        if (e1.w != 0.0f) { c_loc = b1 + 3; v_loc = e1.w; }
        found = __ballot_sync(0xFFFFFFFFu, c_loc >= 0);
    }

    const int src = found ? (__ffs(found) - 1) : 0;
    int   c = __shfl_sync(0xFFFFFFFFu, c_loc, src);
    float v = __shfl_sync(0xFFFFFFFFu, v_loc, src);
    if (c < 0) { c = 0; v = 0.0f; }

    // ---- gather mean_class[c] (L2-hot) and compute ff, pp, fp ----
    const float4* mrow = reinterpret_cast<const float4*>(
        mean_class + (size_t)c * EMBED);
    float4 mv[8];
    #pragma unroll
    for (int k = 0; k < 8; k++) mv[k] = __ldg(&mrow[k * 32 + lane]);

    float ff = 0.0f, pp = 0.0f, fp = 0.0f;
    #pragma unroll
    for (int k = 0; k < 8; k++) {
        const float4 f = fv[k];
        const float4 m = mv[k];
        ff += f.x*f.x + f.y*f.y + f.z*f.z + f.w*f.w;
        pp += m.x*m.x + m.y*m.y + m.z*m.z + m.w*m.w;
        fp += f.x*m.x + f.y*m.y + f.z*m.z + f.w*m.w;
    }
    #pragma unroll
    for (int off = 16; off > 0; off >>= 1) {
        ff += __shfl_xor_sync(0xFFFFFFFFu, ff, off);
        pp += __shfl_xor_sync(0xFFFFFFFFu, pp, off);
        fp += __shfl_xor_sync(0xFFFFFFFFu, fp, off);
    }

    if (lane == 0) {
        const float eps = 1e-12f;
        const float nf   = fmaxf(sqrtf(ff), eps);
        const float np   = fmaxf(fabsf(v) * sqrtf(pp), eps);
        const float cosv = (v * fp) / (nf * np);
        s_part[warp] = 1.0f - cosv;
    }
    __syncthreads();

    // ---- block partial -> global accumulator; last block finishes ----
    if (threadIdx.x == 0) {
        float s = 0.0f;
        #pragma unroll
        for (int w = 0; w < WPB; w++) s += s_part[w];
        atomicAdd(&g_acc, s / (float)N);
        __threadfence();
        const unsigned ticket = atomicAdd(&g_count, 1u);
        if (ticket == (unsigned)(gridDim.x - 1)) {
            out[0] = g_acc;           // all prior adds visible via fence+ticket
            g_acc   = 0.0f;           // reset for next graph replay
            g_count = 0u;
        }
    }
}

extern "C" void kernel_launch(void* const* d_in, const int* in_sizes, int n_in,
                              void* d_out, int out_size)
{
    const float* features   = (const float*)d_in[0];
    const float* labels     = (const float*)d_in[1];
    const float* mean_class = (const float*)d_in[2];
    float* out = (float*)d_out;

    const int N = in_sizes[0] / EMBED;   // 32768

    angular_loss_kernel<<<GRID, THREADS>>>(
        features, labels, mean_class, out, N);
}

// round 9
// speedup vs baseline: 1.3139x; 1.0808x over previous
#include <cuda_runtime.h>
#include <math.h>

#define N_CLASSES 1000
#define L4        250          // label row in float4s (1000/4)
#define EMBED     1024
#define THREADS   256
#define WPB       8            // warps (rows) per block
#define GRID      4096         // 32768 / WPB

__device__ float        g_acc;     // zero-initialized at module load
__device__ unsigned int g_count;   // reset to 0 by last block each run

__global__ void __launch_bounds__(THREADS, 1)
angular_loss_kernel(const float* __restrict__ features,
                    const float* __restrict__ labels,
                    const float* __restrict__ mean_class,
                    float* __restrict__ out,
                    int N)
{
    const int warp = threadIdx.x >> 5;
    const int lane = threadIdx.x & 31;
    const int row  = blockIdx.x * WPB + warp;

    __shared__ float s_part[WPB];

    const float4* lrow = reinterpret_cast<const float4*>(
        labels + (size_t)row * N_CLASSES);
    const float4* frow = reinterpret_cast<const float4*>(
        features + (size_t)row * EMBED);

    // ---- front-batch both DRAM streams, interleaved (16 loads in flight) ----
    float4 lv[8], fv[8];
    #pragma unroll
    for (int k = 0; k < 8; k++) {
        const int idx = k * 32 + lane;
        lv[k] = (idx < L4) ? __ldcs(&lrow[idx]) : make_float4(0.f, 0.f, 0.f, 0.f);
        fv[k] = __ldcs(&frow[idx]);
    }

    // ---- resolve the one-hot (c, v) for this row ----
    int   c_loc = -1;
    float v_loc = 0.0f;
    #pragma unroll
    for (int k = 0; k < 8; k++) {
        const int base = (k * 32 + lane) * 4;
        if (lv[k].x != 0.0f) { c_loc = base + 0; v_loc = lv[k].x; }
        if (lv[k].y != 0.0f) { c_loc = base + 1; v_loc = lv[k].y; }
        if (lv[k].z != 0.0f) { c_loc = base + 2; v_loc = lv[k].z; }
        if (lv[k].w != 0.0f) { c_loc = base + 3; v_loc = lv[k].w; }
    }
    const unsigned found = __ballot_sync(0xFFFFFFFFu, c_loc >= 0);
    const int src = found ? (__ffs(found) - 1) : 0;
    int   c = __shfl_sync(0xFFFFFFFFu, c_loc, src);
    float v = __shfl_sync(0xFFFFFFFFu, v_loc, src);
    if (c < 0) { c = 0; v = 0.0f; }

    // ---- gather mean_class[c] (L2-hot) and compute ff, pp, fp ----
    const float4* mrow = reinterpret_cast<const float4*>(
        mean_class + (size_t)c * EMBED);
    float4 mv[8];
    #pragma unroll
    for (int k = 0; k < 8; k++) mv[k] = __ldg(&mrow[k * 32 + lane]);

    float ff = 0.0f, pp = 0.0f, fp = 0.0f;
    #pragma unroll
    for (int k = 0; k < 8; k++) {
        const float4 f = fv[k];
        const float4 m = mv[k];
        ff += f.x*f.x + f.y*f.y + f.z*f.z + f.w*f.w;
        pp += m.x*m.x + m.y*m.y + m.z*m.z + m.w*m.w;
        fp += f.x*m.x + f.y*m.y + f.z*m.z + f.w*m.w;
    }
    #pragma unroll
    for (int off = 16; off > 0; off >>= 1) {
        ff += __shfl_xor_sync(0xFFFFFFFFu, ff, off);
        pp += __shfl_xor_sync(0xFFFFFFFFu, pp, off);
        fp += __shfl_xor_sync(0xFFFFFFFFu, fp, off);
    }

    if (lane == 0) {
        const float eps = 1e-12f;
        const float nf   = fmaxf(sqrtf(ff), eps);
        const float np   = fmaxf(fabsf(v) * sqrtf(pp), eps);
        const float cosv = (v * fp) / (nf * np);
        s_part[warp] = 1.0f - cosv;
    }
    __syncthreads();

    // ---- block partial -> global accumulator; last block writes d_out ----
    if (threadIdx.x == 0) {
        float s = 0.0f;
        #pragma unroll
        for (int w = 0; w < WPB; w++) s += s_part[w];
        atomicAdd(&g_acc, s / (float)N);
        __threadfence();
        const unsigned ticket = atomicAdd(&g_count, 1u);
        if (ticket == (unsigned)(gridDim.x - 1)) {
            out[0] = g_acc;           // all prior adds visible via fence+ticket
            g_acc   = 0.0f;           // reset for next graph replay
            g_count = 0u;
        }
    }
}

extern "C" void kernel_launch(void* const* d_in, const int* in_sizes, int n_in,
                              void* d_out, int out_size)
{
    const float* features   = (const float*)d_in[0];
    const float* labels     = (const float*)d_in[1];
    const float* mean_class = (const float*)d_in[2];
    float* out = (float*)d_out;

    const int N = in_sizes[0] / EMBED;   // 32768

    angular_loss_kernel<<<GRID, THREADS>>>(
        features, labels, mean_class, out, N);
}

// round 10
// speedup vs baseline: 1.3767x; 1.0478x over previous
#include <cuda_runtime.h>
#include <math.h>

#define N_CLASSES 1000
#define L4        250          // label row in float4s (1000/4)
#define EMBED     1024
#define THREADS   256
#define WPB       8            // warps (rows) per block
#define GRID      4096         // 32768 / WPB

__global__ void zero_out_kernel(float* out) { out[0] = 0.0f; }

__global__ void __launch_bounds__(THREADS, 1)
angular_loss_kernel(const float* __restrict__ features,
                    const float* __restrict__ labels,
                    const float* __restrict__ mean_class,
                    float* __restrict__ out,
                    int N)
{
    const int warp = threadIdx.x >> 5;
    const int lane = threadIdx.x & 31;
    const int row  = blockIdx.x * WPB + warp;

    __shared__ float s_part[WPB];

    const float4* lrow = reinterpret_cast<const float4*>(
        labels + (size_t)row * N_CLASSES);
    const float4* frow = reinterpret_cast<const float4*>(
        features + (size_t)row * EMBED);

    // ---- front batch: ALL labels first (resolve depends on all of them),
    //      then all features. One issue burst, 16 loads in flight; the
    //      dependent mean_class gather overlaps the feature tail.
    float4 lv[8];
    #pragma unroll
    for (int k = 0; k < 8; k++) {
        const int idx = k * 32 + lane;
        lv[k] = (idx < L4) ? __ldcs(&lrow[idx]) : make_float4(0.f, 0.f, 0.f, 0.f);
    }
    float4 fv[8];
    #pragma unroll
    for (int k = 0; k < 8; k++)
        fv[k] = __ldcs(&frow[k * 32 + lane]);

    // ---- resolve the one-hot (c, v) for this row ----
    int   c_loc = -1;
    float v_loc = 0.0f;
    #pragma unroll
    for (int k = 0; k < 8; k++) {
        const int base = (k * 32 + lane) * 4;
        if (lv[k].x != 0.0f) { c_loc = base + 0; v_loc = lv[k].x; }
        if (lv[k].y != 0.0f) { c_loc = base + 1; v_loc = lv[k].y; }
        if (lv[k].z != 0.0f) { c_loc = base + 2; v_loc = lv[k].z; }
        if (lv[k].w != 0.0f) { c_loc = base + 3; v_loc = lv[k].w; }
    }
    const unsigned found = __ballot_sync(0xFFFFFFFFu, c_loc >= 0);
    const int src = found ? (__ffs(found) - 1) : 0;
    int   c = __shfl_sync(0xFFFFFFFFu, c_loc, src);
    float v = __shfl_sync(0xFFFFFFFFu, v_loc, src);
    if (c < 0) { c = 0; v = 0.0f; }

    // ---- gather mean_class[c] (L2-hot); overlaps in-flight feature loads ----
    const float4* mrow = reinterpret_cast<const float4*>(
        mean_class + (size_t)c * EMBED);
    float4 mv[8];
    #pragma unroll
    for (int k = 0; k < 8; k++) mv[k] = __ldg(&mrow[k * 32 + lane]);

    float ff = 0.0f, pp = 0.0f, fp = 0.0f;
    #pragma unroll
    for (int k = 0; k < 8; k++) {
        const float4 f = fv[k];
        const float4 m = mv[k];
        ff += f.x*f.x + f.y*f.y + f.z*f.z + f.w*f.w;
        pp += m.x*m.x + m.y*m.y + m.z*m.z + m.w*m.w;
        fp += f.x*m.x + f.y*m.y + f.z*m.z + f.w*m.w;
    }
    #pragma unroll
    for (int off = 16; off > 0; off >>= 1) {
        ff += __shfl_xor_sync(0xFFFFFFFFu, ff, off);
        pp += __shfl_xor_sync(0xFFFFFFFFu, pp, off);
        fp += __shfl_xor_sync(0xFFFFFFFFu, fp, off);
    }

    if (lane == 0) {
        const float eps = 1e-12f;
        const float nf   = fmaxf(sqrtf(ff), eps);
        const float np   = fmaxf(fabsf(v) * sqrtf(pp), eps);
        const float cosv = (v * fp) / (nf * np);
        s_part[warp] = 1.0f - cosv;
    }
    __syncthreads();

    if (threadIdx.x == 0) {
        float s = 0.0f;
        #pragma unroll
        for (int w = 0; w < WPB; w++) s += s_part[w];
        atomicAdd(out, s / (float)N);
    }
}

extern "C" void kernel_launch(void* const* d_in, const int* in_sizes, int n_in,
                              void* d_out, int out_size)
{
    const float* features   = (const float*)d_in[0];
    const float* labels     = (const float*)d_in[1];
    const float* mean_class = (const float*)d_in[2];
    float* out = (float*)d_out;

    const int N = in_sizes[0] / EMBED;   // 32768

    zero_out_kernel<<<1, 1>>>(out);
    angular_loss_kernel<<<GRID, THREADS>>>(
        features, labels, mean_class, out, N);
}

// round 11
// speedup vs baseline: 1.3880x; 1.0082x over previous
#include <cuda_runtime.h>
#include <math.h>

#define N_CLASSES 1000
#define L4        250          // label row in float4s (1000/4)
#define EMBED     1024
#define THREADS   128
#define WPB       4            // warps (rows) per block
#define GRID      8192         // 32768 / WPB

__global__ void zero_out_kernel(float* out) { out[0] = 0.0f; }

__global__ void __launch_bounds__(THREADS, 1)
angular_loss_kernel(const float* __restrict__ features,
                    const float* __restrict__ labels,
                    const float* __restrict__ mean_class,
                    float* __restrict__ out,
                    int N)
{
    const int warp = threadIdx.x >> 5;
    const int lane = threadIdx.x & 31;
    const int row  = blockIdx.x * WPB + warp;

    __shared__ float s_part[WPB];

    const float4* lrow = reinterpret_cast<const float4*>(
        labels + (size_t)row * N_CLASSES);
    const float4* frow = reinterpret_cast<const float4*>(
        features + (size_t)row * EMBED);

    // ---- front-batch both DRAM streams, interleaved (16 loads in flight) ----
    float4 lv[8], fv[8];
    #pragma unroll
    for (int k = 0; k < 8; k++) {
        const int idx = k * 32 + lane;
        lv[k] = (idx < L4) ? __ldcs(&lrow[idx]) : make_float4(0.f, 0.f, 0.f, 0.f);
        fv[k] = __ldcs(&frow[idx]);
    }

    // ---- resolve the one-hot (c, v) for this row ----
    int   c_loc = -1;
    float v_loc = 0.0f;
    #pragma unroll
    for (int k = 0; k < 8; k++) {
        const int base = (k * 32 + lane) * 4;
        if (lv[k].x != 0.0f) { c_loc = base + 0; v_loc = lv[k].x; }
        if (lv[k].y != 0.0f) { c_loc = base + 1; v_loc = lv[k].y; }
        if (lv[k].z != 0.0f) { c_loc = base + 2; v_loc = lv[k].z; }
        if (lv[k].w != 0.0f) { c_loc = base + 3; v_loc = lv[k].w; }
    }
    const unsigned found = __ballot_sync(0xFFFFFFFFu, c_loc >= 0);
    const int src = found ? (__ffs(found) - 1) : 0;
    int   c = __shfl_sync(0xFFFFFFFFu, c_loc, src);
    float v = __shfl_sync(0xFFFFFFFFu, v_loc, src);
    if (c < 0) { c = 0; v = 0.0f; }

    // ---- gather mean_class[c] (L2-hot) and compute ff, pp, fp ----
    const float4* mrow = reinterpret_cast<const float4*>(
        mean_class + (size_t)c * EMBED);
    float4 mv[8];
    #pragma unroll
    for (int k = 0; k < 8; k++) mv[k] = __ldg(&mrow[k * 32 + lane]);

    float ff = 0.0f, pp = 0.0f, fp = 0.0f;
    #pragma unroll
    for (int k = 0; k < 8; k++) {
        const float4 f = fv[k];
        const float4 m = mv[k];
        ff += f.x*f.x + f.y*f.y + f.z*f.z + f.w*f.w;
        pp += m.x*m.x + m.y*m.y + m.z*m.z + m.w*m.w;
        fp += f.x*m.x + f.y*m.y + f.z*m.z + f.w*m.w;
    }
    #pragma unroll
    for (int off = 16; off > 0; off >>= 1) {
        ff += __shfl_xor_sync(0xFFFFFFFFu, ff, off);
        pp += __shfl_xor_sync(0xFFFFFFFFu, pp, off);
        fp += __shfl_xor_sync(0xFFFFFFFFu, fp, off);
    }

    if (lane == 0) {
        const float eps = 1e-12f;
        const float nf   = fmaxf(sqrtf(ff), eps);
        const float np   = fmaxf(fabsf(v) * sqrtf(pp), eps);
        const float cosv = (v * fp) / (nf * np);
        s_part[warp] = 1.0f - cosv;
    }
    __syncthreads();

    if (threadIdx.x == 0) {
        float s = (s_part[0] + s_part[1]) + (s_part[2] + s_part[3]);
        atomicAdd(out, s / (float)N);
    }
}

extern "C" void kernel_launch(void* const* d_in, const int* in_sizes, int n_in,
                              void* d_out, int out_size)
{
    const float* features   = (const float*)d_in[0];
    const float* labels     = (const float*)d_in[1];
    const float* mean_class = (const float*)d_in[2];
    float* out = (float*)d_out;

    const int N = in_sizes[0] / EMBED;   // 32768

    zero_out_kernel<<<1, 1>>>(out);
    angular_loss_kernel<<<GRID, THREADS>>>(
        features, labels, mean_class, out, N);
}